// round 11
// baseline (speedup 1.0000x reference)
#include <cuda_runtime.h>
#include <cuda_bf16.h>
#include <mma.h>
#include <cstdint>
using namespace nvcuda;

#define NC 200
#define NA 768
#define NB 256
#define KTOT (NA * NA)
#define MPAD 512

__device__ int   g_cnt[NC];
__device__ int   g_items[NC * 256];
__device__ float g_w[NC];
__device__ float g_ave[NC * NA];
__device__ float g_dvec[NC * NA];
__device__ float g_qcov[2 * NC * NC];
__device__ float g_qlow[2 * NC * NC];
__device__ float g_ce[NB];
__device__ float g_kl[NB];
__device__ float g_ws[MPAD * NA];
__device__ __nv_bfloat16 g_wb[MPAD * NA];
__device__ __nv_bfloat16 g_covh[(size_t)NC * KTOT];
__device__ float g_D[(size_t)NC * 400 * NA];

__device__ __forceinline__ uint32_t f2bf2(float a, float b) {
    __nv_bfloat162 t = __floats2bfloat162_rn(a, b);
    return *(uint32_t*)&t;
}

__global__ void k_stats(const float* __restrict__ feat, const float* __restrict__ Ave,
                        const float* __restrict__ Amount, const int* __restrict__ tgt) {
    int c = blockIdx.x;
    __shared__ int s_cnt;
    if (threadIdx.x == 0) {
        int k = 0;
        for (int n = 0; n < NB; ++n)
            if (tgt[n] == c) g_items[c * 256 + (k++)] = n;
        s_cnt = k; g_cnt[c] = k;
        float amt = (float)k, den = amt + Amount[c];
        g_w[c] = (den > 0.f) ? (amt / den) : 0.f;
    }
    __syncthreads();
    int cnt = s_cnt;
    float inv = 1.f / fmaxf((float)cnt, 1.f);
    for (int a = threadIdx.x; a < NA; a += blockDim.x) {
        float s = 0.f;
        for (int k = 0; k < cnt; ++k) s += feat[g_items[c * 256 + k] * NA + a];
        float av = s * inv;
        g_ave[c * NA + a]  = av;
        g_dvec[c * NA + a] = Ave[c * NA + a] - av;
    }
}

__global__ void k_wconv(const float* __restrict__ wfc, const float* __restrict__ wfct) {
    int r = blockIdx.x;
    for (int a = threadIdx.x; a < NA; a += blockDim.x) {
        float v = 0.f;
        if (r < NC)          v = wfc[r * NA + a];
        else if (r < 2 * NC) v = wfct[(r - NC) * NA + a];
        g_ws[r * NA + a] = v;
        g_wb[r * NA + a] = __float2bfloat16(v);
    }
}

__global__ void k_covcvt(const float* __restrict__ CoV) {
    if (g_cnt[blockIdx.x] == 0) return;
    size_t cbase = (size_t)blockIdx.x * KTOT;
    const float4* src = (const float4*)(CoV + cbase) + blockIdx.y * 4096;
    uint2* dst = (uint2*)(g_covh + cbase) + blockIdx.y * 4096;
    int tid = threadIdx.x;
    #pragma unroll
    for (int k = 0; k < 16; ++k) {
        float4 v = src[tid + k * 256];
        uint2 p;
        p.x = f2bf2(v.x, v.y);
        p.y = f2bf2(v.z, v.w);
        dst[tid + k * 256] = p;
    }
}

__global__ void k_y(const float* __restrict__ feat, const float* __restrict__ wfc,
                    const float* __restrict__ bfc, float* __restrict__ out) {
    int n0 = blockIdx.x * 8;
    __shared__ float sf[8][NA];
    int tid = threadIdx.x;
    for (int idx = tid; idx < 8 * NA; idx += 256)
        sf[idx / NA][idx % NA] = feat[(n0 + idx / NA) * NA + idx % NA];
    __syncthreads();
    int lane = tid & 31, wid = tid >> 5;
    for (int c = wid; c < NC; c += 8) {
        float wreg[24];
        #pragma unroll
        for (int i = 0; i < 24; ++i) wreg[i] = wfc[c * NA + i * 32 + lane];
        float bc = bfc[c];
        for (int r = 0; r < 8; ++r) {
            float acc = 0.f;
            #pragma unroll
            for (int i = 0; i < 24; ++i) acc += wreg[i] * sf[r][i * 32 + lane];
            #pragma unroll
            for (int o = 16; o; o >>= 1) acc += __shfl_xor_sync(0xffffffffu, acc, o);
            if (lane == 0) out[1 + (n0 + r) * NC + c] = acc + bc;
        }
    }
}

// ---- batched GEMM: D_c[r][a] = sum_b covh[c][a][b] * wb[r][b] --------------
// grid (24, NC): at = x>>2 (6 a-tiles of 128), rt = x&3 (4 r-tiles of 128)
// 128 threads, warp tile 64x64 (2x2 warps), 3-stage cp.async, 1 sync/chunk.
#define STG 36864            // (128 + 128) rows * 144B per stage
#define ABUF 18432
#define LDH 72

__global__ __launch_bounds__(128) void k_gemm2() {
    extern __shared__ char smem[];
    const int c = blockIdx.y;
    if (g_cnt[c] == 0) return;
    const int at = blockIdx.x >> 2, rt = blockIdx.x & 3;
    const int tid = threadIdx.x, wid = tid >> 5;
    const int wm = (wid & 1) * 64;          // a offset
    const int wn = (wid >> 1) * 64;         // r offset
    int rlim = 400 - (rt * 128 + wn);
    int jmax = (rlim + 15) >> 4;
    if (jmax < 0) jmax = 0; if (jmax > 4) jmax = 4;

    const uint32_t sbase = (uint32_t)__cvta_generic_to_shared(smem);
    const char* srcA = (const char*)g_covh +
        2 * ((size_t)c * KTOT + (size_t)(at * 128 + tid) * NA);
    const char* srcB = (const char*)g_wb + 2 * (size_t)(rt * 128 + tid) * NA;
    const uint32_t dA = sbase + tid * 144;
    const uint32_t dB = sbase + ABUF + tid * 144;

    #define ISSUE(CH) do {                                                       \
        uint32_t _o = ((CH) % 3) * STG;                                          \
        const char* _sa = srcA + (size_t)(CH) * 128;                             \
        const char* _sb = srcB + (size_t)(CH) * 128;                             \
        _Pragma("unroll")                                                        \
        for (int q = 0; q < 8; ++q)                                              \
            asm volatile("cp.async.cg.shared.global [%0], [%1], 16;"             \
                :: "r"(dA + _o + q * 16), "l"(_sa + q * 16));                    \
        _Pragma("unroll")                                                        \
        for (int q = 0; q < 8; ++q)                                              \
            asm volatile("cp.async.cg.shared.global [%0], [%1], 16;"             \
                :: "r"(dB + _o + q * 16), "l"(_sb + q * 16));                    \
        asm volatile("cp.async.commit_group;");                                  \
    } while (0)

    wmma::fragment<wmma::accumulator, 16, 16, 16, float> fc[4][4];
    #pragma unroll
    for (int i = 0; i < 4; ++i)
        #pragma unroll
        for (int j = 0; j < 4; ++j) wmma::fill_fragment(fc[i][j], 0.f);

    ISSUE(0);
    ISSUE(1);
    for (int ch = 0; ch < 12; ++ch) {
        if (ch < 11) asm volatile("cp.async.wait_group 1;");
        else         asm volatile("cp.async.wait_group 0;");
        __syncthreads();
        if (ch + 2 < 12) ISSUE(ch + 2);
        const __nv_bfloat16* sA = (const __nv_bfloat16*)(smem + (ch % 3) * STG);
        const __nv_bfloat16* sB = (const __nv_bfloat16*)(smem + (ch % 3) * STG + ABUF);
        if (jmax > 0) {
            #pragma unroll
            for (int kk = 0; kk < 64; kk += 16) {
                wmma::fragment<wmma::matrix_a, 16, 16, 16, __nv_bfloat16, wmma::row_major> fa[4];
                #pragma unroll
                for (int i = 0; i < 4; ++i)
                    wmma::load_matrix_sync(fa[i], sA + (wm + i * 16) * LDH + kk, LDH);
                for (int j = 0; j < jmax; ++j) {
                    wmma::fragment<wmma::matrix_b, 16, 16, 16, __nv_bfloat16, wmma::col_major> fb;
                    wmma::load_matrix_sync(fb, sB + (wn + j * 16) * LDH + kk, LDH);
                    #pragma unroll
                    for (int i = 0; i < 4; ++i)
                        wmma::mma_sync(fc[i][j], fa[i], fb, fc[i][j]);
                }
            }
        }
    }
    #undef ISSUE

    float* Dc = g_D + (size_t)c * 400 * NA;
    for (int j = 0; j < jmax; ++j) {
        int r0 = rt * 128 + wn + j * 16;
        if (r0 < 400) {
            #pragma unroll
            for (int i = 0; i < 4; ++i)
                wmma::store_matrix_sync(Dc + (size_t)r0 * NA + at * 128 + wm + i * 16,
                                        fc[i][j], NA, wmma::mem_col_major);
        }
    }
}

// ---- epilogue: qcov = t1 - cross1 - cross2 + self --------------------------
__global__ __launch_bounds__(256) void k_post() {
    int c = blockIdx.x;
    if (g_cnt[c] == 0) return;
    int rbase = blockIdx.y * 100;
    int tid = threadIdx.x, lane = tid & 31, wid = tid >> 5;
    __shared__ float sw[2][NA];
    __shared__ float sd[2][NA];
    __shared__ float red[256];
    __shared__ float s_self[2];
    const float* D0 = g_D + ((size_t)c * 400 + c) * NA;
    const float* D1 = g_D + ((size_t)c * 400 + NC + c) * NA;
    for (int a = tid; a < NA; a += 256) {
        sw[0][a] = g_ws[c * NA + a];
        sw[1][a] = g_ws[(NC + c) * NA + a];
        sd[0][a] = D0[a];
        sd[1][a] = D1[a];
    }
    __syncthreads();
    for (int m = 0; m < 2; ++m) {
        float p = 0.f;
        for (int a = tid; a < NA; a += 256) p += sw[m][a] * sd[m][a];
        red[tid] = p; __syncthreads();
        for (int s = 128; s; s >>= 1) { if (tid < s) red[tid] += red[tid + s]; __syncthreads(); }
        if (tid == 0) s_self[m] = red[0];
        __syncthreads();
    }
    for (int r = rbase + wid; r < rbase + 100; r += 8) {
        int m = (r < NC) ? 0 : 1;
        int cp = r - m * NC;
        const float* Dr = g_D + ((size_t)c * 400 + r) * NA;
        const float* Wr = g_ws + r * NA;
        float t1 = 0.f, c1 = 0.f, c2 = 0.f;
        for (int a = lane; a < NA; a += 32) {
            float dv = Dr[a], wv = Wr[a];
            t1 += wv * dv;
            c2 += sw[m][a] * dv;
            c1 += wv * sd[m][a];
        }
        #pragma unroll
        for (int o = 16; o; o >>= 1) {
            t1 += __shfl_xor_sync(0xffffffffu, t1, o);
            c1 += __shfl_xor_sync(0xffffffffu, c1, o);
            c2 += __shfl_xor_sync(0xffffffffu, c2, o);
        }
        if (lane == 0)
            g_qcov[m * NC * NC + c * NC + cp] = t1 - c1 - c2 + s_self[m];
    }
}

__global__ void k_lowrank(const float* __restrict__ feat, const float* __restrict__ wfc,
                          const float* __restrict__ wfct) {
    int c = blockIdx.x, m = blockIdx.y;
    int cnt = g_cnt[c];
    if (cnt == 0) return;
    float w = g_w[c];
    float amt = (float)cnt;
    int lane = threadIdx.x & 31, wid = threadIdx.x >> 5;
    const float* W = m ? wfct : wfc;
    for (int cp = wid; cp < NC; cp += 8) {
        float ssum = 0.f, dd = 0.f;
        for (int v = 0; v <= cnt; ++v) {
            float acc = 0.f;
            if (v < cnt) {
                const float* f = feat + g_items[c * 256 + v] * NA;
                for (int a = lane; a < NA; a += 32)
                    acc += (W[cp * NA + a] - W[c * NA + a]) * (f[a] - g_ave[c * NA + a]);
            } else {
                for (int a = lane; a < NA; a += 32)
                    acc += (W[cp * NA + a] - W[c * NA + a]) * g_dvec[c * NA + a];
            }
            #pragma unroll
            for (int o = 16; o; o >>= 1) acc += __shfl_xor_sync(0xffffffffu, acc, o);
            if (v < cnt) ssum += acc * acc; else dd = acc * acc;
        }
        if (lane == 0)
            g_qlow[m * NC * NC + c * NC + cp] = (w / amt) * ssum + w * (1.f - w) * dd;
    }
}

__device__ __forceinline__ float blk_max(float v, float* red) {
    int t = threadIdx.x;
    red[t] = v; __syncthreads();
    for (int s = 128; s; s >>= 1) { if (t < s) red[t] = fmaxf(red[t], red[t + s]); __syncthreads(); }
    float r = red[0]; __syncthreads(); return r;
}
__device__ __forceinline__ float blk_sum(float v, float* red) {
    int t = threadIdx.x;
    red[t] = v; __syncthreads();
    for (int s = 128; s; s >>= 1) { if (t < s) red[t] += red[t + s]; __syncthreads(); }
    float r = red[0]; __syncthreads(); return r;
}

__global__ void k_loss(const float* __restrict__ out, const int* __restrict__ tgt,
                       const float* __restrict__ ratio_p) {
    int n = blockIdx.x;
    int c = threadIdx.x;
    bool valid = (c < NC);
    int yn = tgt[n];
    float wy = g_w[yn];
    float ratio = ratio_p[0];
    __shared__ float red[256];
    float aug = -1e30f, augt = -1e30f;
    if (valid) {
        float yv = out[1 + n * NC + c];
        float q1 = (1.f - wy) * g_qcov[yn * NC + c] + g_qlow[yn * NC + c];
        float q2 = (1.f - wy) * g_qcov[NC * NC + yn * NC + c] + g_qlow[NC * NC + yn * NC + c];
        aug  = yv + 0.5f * ratio * q1;
        augt = yv + 0.5f * ratio * q2;
    }
    float mx  = blk_max(aug,  red);
    float mxt = blk_max(augt, red);
    float sa = blk_sum(valid ? expf(aug  - mx)  : 0.f, red);
    float sb = blk_sum(valid ? expf(augt - mxt) : 0.f, red);
    float lp  = aug  - mx  - logf(sa);
    float lpt = augt - mxt - logf(sb);
    float pt  = valid ? expf(lpt) : 0.f;
    float kln = blk_sum(valid ? pt * (lpt - lp) : 0.f, red);
    if (threadIdx.x == 0) g_kl[n] = kln;
    if (valid && c == yn) g_ce[n] = -lp;
}

__global__ void k_final(float* __restrict__ out) {
    __shared__ float red[256];
    int t = threadIdx.x;
    float v = g_ce[t] * (1.f / (float)NB) + g_kl[t] * (1.f / ((float)NB * (float)NC));
    red[t] = v; __syncthreads();
    for (int s = 128; s; s >>= 1) { if (t < s) red[t] += red[t + s]; __syncthreads(); }
    if (t == 0) out[0] = red[0];
}

extern "C" void kernel_launch(void* const* d_in, const int* in_sizes, int n_in,
                              void* d_out, int out_size) {
    const float* feat  = (const float*)d_in[0];
    const float* wfc   = (const float*)d_in[1];
    const float* bfc   = (const float*)d_in[2];
    const float* wfct  = (const float*)d_in[3];
    const float* cov   = (const float*)d_in[4];
    const float* Ave   = (const float*)d_in[5];
    const float* Amt   = (const float*)d_in[6];
    const int*   tgt   = (const int*)d_in[7];
    const float* ratio = (const float*)d_in[8];
    float* out = (float*)d_out;

    static bool init_done = false;
    static cudaStream_t sB;
    static cudaEvent_t evFork, evStats, evC;
    if (!init_done) {
        cudaFuncSetAttribute(k_gemm2, cudaFuncAttributeMaxDynamicSharedMemorySize, 3 * STG);
        cudaStreamCreateWithFlags(&sB, cudaStreamNonBlocking);
        cudaEventCreateWithFlags(&evFork, cudaEventDisableTiming);
        cudaEventCreateWithFlags(&evStats, cudaEventDisableTiming);
        cudaEventCreateWithFlags(&evC, cudaEventDisableTiming);
        init_done = true;
    }

    cudaEventRecord(evFork, 0);

    k_stats  <<<NC, 256>>>(feat, Ave, Amt, tgt);
    cudaEventRecord(evStats, 0);
    k_wconv  <<<MPAD, 256>>>(wfc, wfct);
    k_covcvt <<<dim3(NC, 36), 256>>>(cov);
    k_gemm2  <<<dim3(24, NC), 128, 3 * STG>>>();
    k_post   <<<dim3(NC, 4), 256>>>();

    cudaStreamWaitEvent(sB, evFork, 0);
    k_y      <<<32, 256, 0, sB>>>(feat, wfc, bfc, out);
    cudaStreamWaitEvent(sB, evStats, 0);
    k_lowrank<<<dim3(NC, 2), 256, 0, sB>>>(feat, wfc, wfct);
    cudaEventRecord(evC, sB);

    cudaStreamWaitEvent(0, evC, 0);
    k_loss   <<<NB, 256>>>(out, tgt, ratio);
    k_final  <<<1, 256>>>(out);
}

// round 12
// speedup vs baseline: 1.2327x; 1.2327x over previous
#include <cuda_runtime.h>
#include <cuda_bf16.h>
#include <mma.h>
#include <cstdint>
using namespace nvcuda;

#define NC 200
#define NA 768
#define NB 256
#define KTOT (NA * NA)
#define MPAD 512

__device__ int   g_cnt[NC];
__device__ int   g_items[NC * 256];
__device__ float g_w[NC];
__device__ float g_ave[NC * NA];
__device__ float g_dvec[NC * NA];
__device__ float g_qcov[2 * NC * NC];
__device__ float g_qlow[2 * NC * NC];
__device__ float g_ce[NB];
__device__ float g_kl[NB];
__device__ float g_ws[MPAD * NA];
__device__ __nv_bfloat16 g_wb[MPAD * NA];
__device__ __nv_bfloat16 g_covh[(size_t)NC * KTOT];
__device__ float g_D[(size_t)NC * 400 * NA];

__device__ __forceinline__ uint32_t f2bf2(float a, float b) {
    __nv_bfloat162 t = __floats2bfloat162_rn(a, b);
    return *(uint32_t*)&t;
}

__global__ void k_stats(const float* __restrict__ feat, const float* __restrict__ Ave,
                        const float* __restrict__ Amount, const int* __restrict__ tgt) {
    int c = blockIdx.x;
    __shared__ int s_cnt;
    if (threadIdx.x == 0) {
        int k = 0;
        for (int n = 0; n < NB; ++n)
            if (tgt[n] == c) g_items[c * 256 + (k++)] = n;
        s_cnt = k; g_cnt[c] = k;
        float amt = (float)k, den = amt + Amount[c];
        g_w[c] = (den > 0.f) ? (amt / den) : 0.f;
    }
    __syncthreads();
    int cnt = s_cnt;
    float inv = 1.f / fmaxf((float)cnt, 1.f);
    for (int a = threadIdx.x; a < NA; a += blockDim.x) {
        float s = 0.f;
        for (int k = 0; k < cnt; ++k) s += feat[g_items[c * 256 + k] * NA + a];
        float av = s * inv;
        g_ave[c * NA + a]  = av;
        g_dvec[c * NA + a] = Ave[c * NA + a] - av;
    }
}

__global__ void k_wconv(const float* __restrict__ wfc, const float* __restrict__ wfct) {
    int r = blockIdx.x;
    for (int a = threadIdx.x; a < NA; a += blockDim.x) {
        float v = 0.f;
        if (r < NC)          v = wfc[r * NA + a];
        else if (r < 2 * NC) v = wfct[(r - NC) * NA + a];
        g_ws[r * NA + a] = v;
        g_wb[r * NA + a] = __float2bfloat16(v);
    }
}

__global__ void k_covcvt(const float* __restrict__ CoV) {
    if (g_cnt[blockIdx.x] == 0) return;
    size_t cbase = (size_t)blockIdx.x * KTOT;
    const float4* src = (const float4*)(CoV + cbase) + blockIdx.y * 4096;
    uint2* dst = (uint2*)(g_covh + cbase) + blockIdx.y * 4096;
    int tid = threadIdx.x;
    #pragma unroll
    for (int k = 0; k < 16; ++k) {
        float4 v = src[tid + k * 256];
        uint2 p;
        p.x = f2bf2(v.x, v.y);
        p.y = f2bf2(v.z, v.w);
        dst[tid + k * 256] = p;
    }
}

__global__ void k_y(const float* __restrict__ feat, const float* __restrict__ wfc,
                    const float* __restrict__ bfc, float* __restrict__ out) {
    int n0 = blockIdx.x * 8;
    __shared__ float sf[8][NA];
    int tid = threadIdx.x;
    for (int idx = tid; idx < 8 * NA; idx += 256)
        sf[idx / NA][idx % NA] = feat[(n0 + idx / NA) * NA + idx % NA];
    __syncthreads();
    int lane = tid & 31, wid = tid >> 5;
    for (int c = wid; c < NC; c += 8) {
        float wreg[24];
        #pragma unroll
        for (int i = 0; i < 24; ++i) wreg[i] = wfc[c * NA + i * 32 + lane];
        float bc = bfc[c];
        for (int r = 0; r < 8; ++r) {
            float acc = 0.f;
            #pragma unroll
            for (int i = 0; i < 24; ++i) acc += wreg[i] * sf[r][i * 32 + lane];
            #pragma unroll
            for (int o = 16; o; o >>= 1) acc += __shfl_xor_sync(0xffffffffu, acc, o);
            if (lane == 0) out[1 + (n0 + r) * NC + c] = acc + bc;
        }
    }
}

// ---- batched GEMM: D_c[r][a] = sum_b covh[c][a][b] * wb[r][b] --------------
// grid (12, NC): at = x>>1 (6 a-tiles of 128), rt = x&1 (2 r-tiles of 256)
// 256 threads, warp tile 64x64 (2x4 warps), 3-stage cp.async, 1 sync/chunk.
#define ABUF 18432            // 128 * 144B
#define BBUF 36864            // 256 * 144B
#define CBUF (ABUF + BBUF)    // 55296 per stage
#define LDH 72

__global__ __launch_bounds__(256) void k_gemm2() {
    extern __shared__ char smem[];
    const int c = blockIdx.y;
    if (g_cnt[c] == 0) return;
    const int at = blockIdx.x >> 1, rt = blockIdx.x & 1;
    const int tid = threadIdx.x, wid = tid >> 5;
    const int wm = (wid & 1) * 64;          // a offset in tile
    const int wn = (wid >> 1) * 64;         // r offset in tile
    int rlim = 400 - (rt * 256 + wn);
    int jmax = (rlim + 15) >> 4;
    if (jmax < 0) jmax = 0; if (jmax > 4) jmax = 4;

    const int rowA = tid >> 1, halfA = tid & 1;
    const uint32_t sbase = (uint32_t)__cvta_generic_to_shared(smem);
    const char* srcA = (const char*)g_covh +
        2 * ((size_t)c * KTOT + (size_t)(at * 128 + rowA) * NA) + halfA * 64;
    const char* srcB = (const char*)g_wb + 2 * (size_t)(rt * 256 + tid) * NA;
    const uint32_t dA = sbase + rowA * 144 + halfA * 64;
    const uint32_t dB = sbase + ABUF + tid * 144;

    #define ISSUE(CH) do {                                                       \
        uint32_t _o = ((CH) % 3) * CBUF;                                         \
        const char* _sa = srcA + (size_t)(CH) * 128;                             \
        const char* _sb = srcB + (size_t)(CH) * 128;                             \
        _Pragma("unroll")                                                        \
        for (int q = 0; q < 4; ++q)                                              \
            asm volatile("cp.async.cg.shared.global [%0], [%1], 16;"             \
                :: "r"(dA + _o + q * 16), "l"(_sa + q * 16));                    \
        _Pragma("unroll")                                                        \
        for (int q = 0; q < 8; ++q)                                              \
            asm volatile("cp.async.cg.shared.global [%0], [%1], 16;"             \
                :: "r"(dB + _o + q * 16), "l"(_sb + q * 16));                    \
        asm volatile("cp.async.commit_group;");                                  \
    } while (0)

    wmma::fragment<wmma::accumulator, 16, 16, 16, float> fc[4][4];
    #pragma unroll
    for (int i = 0; i < 4; ++i)
        #pragma unroll
        for (int j = 0; j < 4; ++j) wmma::fill_fragment(fc[i][j], 0.f);

    ISSUE(0);
    ISSUE(1);
    for (int ch = 0; ch < 12; ++ch) {
        if (ch < 11) asm volatile("cp.async.wait_group 1;");
        else         asm volatile("cp.async.wait_group 0;");
        __syncthreads();
        if (ch + 2 < 12) ISSUE(ch + 2);
        const __nv_bfloat16* sA = (const __nv_bfloat16*)(smem + (ch % 3) * CBUF);
        const __nv_bfloat16* sB = (const __nv_bfloat16*)(smem + (ch % 3) * CBUF + ABUF);
        if (jmax > 0) {
            #pragma unroll
            for (int kk = 0; kk < 64; kk += 16) {
                wmma::fragment<wmma::matrix_a, 16, 16, 16, __nv_bfloat16, wmma::row_major> fa[4];
                #pragma unroll
                for (int i = 0; i < 4; ++i)
                    wmma::load_matrix_sync(fa[i], sA + (wm + i * 16) * LDH + kk, LDH);
                for (int j = 0; j < jmax; ++j) {
                    wmma::fragment<wmma::matrix_b, 16, 16, 16, __nv_bfloat16, wmma::col_major> fb;
                    wmma::load_matrix_sync(fb, sB + (wn + j * 16) * LDH + kk, LDH);
                    #pragma unroll
                    for (int i = 0; i < 4; ++i)
                        wmma::mma_sync(fc[i][j], fa[i], fb, fc[i][j]);
                }
            }
        }
    }
    #undef ISSUE

    float* Dc = g_D + (size_t)c * 400 * NA;
    for (int j = 0; j < jmax; ++j) {
        int r0 = rt * 256 + wn + j * 16;
        if (r0 < 400) {
            #pragma unroll
            for (int i = 0; i < 4; ++i)
                wmma::store_matrix_sync(Dc + (size_t)r0 * NA + at * 128 + wm + i * 16,
                                        fc[i][j], NA, wmma::mem_col_major);
        }
    }
}

// ---- epilogue: qcov = t1 - cross1 - cross2 + self --------------------------
__global__ __launch_bounds__(256) void k_post() {
    int c = blockIdx.x;
    if (g_cnt[c] == 0) return;
    int rbase = blockIdx.y * 100;
    int tid = threadIdx.x, lane = tid & 31, wid = tid >> 5;
    __shared__ float sw[2][NA];
    __shared__ float sd[2][NA];
    __shared__ float red[256];
    __shared__ float s_self[2];
    const float* D0 = g_D + ((size_t)c * 400 + c) * NA;
    const float* D1 = g_D + ((size_t)c * 400 + NC + c) * NA;
    for (int a = tid; a < NA; a += 256) {
        sw[0][a] = g_ws[c * NA + a];
        sw[1][a] = g_ws[(NC + c) * NA + a];
        sd[0][a] = D0[a];
        sd[1][a] = D1[a];
    }
    __syncthreads();
    for (int m = 0; m < 2; ++m) {
        float p = 0.f;
        for (int a = tid; a < NA; a += 256) p += sw[m][a] * sd[m][a];
        red[tid] = p; __syncthreads();
        for (int s = 128; s; s >>= 1) { if (tid < s) red[tid] += red[tid + s]; __syncthreads(); }
        if (tid == 0) s_self[m] = red[0];
        __syncthreads();
    }
    for (int r = rbase + wid; r < rbase + 100; r += 8) {
        int m = (r < NC) ? 0 : 1;
        int cp = r - m * NC;
        const float* Dr = g_D + ((size_t)c * 400 + r) * NA;
        const float* Wr = g_ws + r * NA;
        float t1 = 0.f, c1 = 0.f, c2 = 0.f;
        for (int a = lane; a < NA; a += 32) {
            float dv = Dr[a], wv = Wr[a];
            t1 += wv * dv;
            c2 += sw[m][a] * dv;
            c1 += wv * sd[m][a];
        }
        #pragma unroll
        for (int o = 16; o; o >>= 1) {
            t1 += __shfl_xor_sync(0xffffffffu, t1, o);
            c1 += __shfl_xor_sync(0xffffffffu, c1, o);
            c2 += __shfl_xor_sync(0xffffffffu, c2, o);
        }
        if (lane == 0)
            g_qcov[m * NC * NC + c * NC + cp] = t1 - c1 - c2 + s_self[m];
    }
}

__global__ void k_lowrank(const float* __restrict__ feat, const float* __restrict__ wfc,
                          const float* __restrict__ wfct) {
    int c = blockIdx.x, m = blockIdx.y;
    int cnt = g_cnt[c];
    if (cnt == 0) return;
    float w = g_w[c];
    float amt = (float)cnt;
    int lane = threadIdx.x & 31, wid = threadIdx.x >> 5;
    const float* W = m ? wfct : wfc;
    for (int cp = wid; cp < NC; cp += 8) {
        float ssum = 0.f, dd = 0.f;
        for (int v = 0; v <= cnt; ++v) {
            float acc = 0.f;
            if (v < cnt) {
                const float* f = feat + g_items[c * 256 + v] * NA;
                for (int a = lane; a < NA; a += 32)
                    acc += (W[cp * NA + a] - W[c * NA + a]) * (f[a] - g_ave[c * NA + a]);
            } else {
                for (int a = lane; a < NA; a += 32)
                    acc += (W[cp * NA + a] - W[c * NA + a]) * g_dvec[c * NA + a];
            }
            #pragma unroll
            for (int o = 16; o; o >>= 1) acc += __shfl_xor_sync(0xffffffffu, acc, o);
            if (v < cnt) ssum += acc * acc; else dd = acc * acc;
        }
        if (lane == 0)
            g_qlow[m * NC * NC + c * NC + cp] = (w / amt) * ssum + w * (1.f - w) * dd;
    }
}

__device__ __forceinline__ float blk_max(float v, float* red) {
    int t = threadIdx.x;
    red[t] = v; __syncthreads();
    for (int s = 128; s; s >>= 1) { if (t < s) red[t] = fmaxf(red[t], red[t + s]); __syncthreads(); }
    float r = red[0]; __syncthreads(); return r;
}
__device__ __forceinline__ float blk_sum(float v, float* red) {
    int t = threadIdx.x;
    red[t] = v; __syncthreads();
    for (int s = 128; s; s >>= 1) { if (t < s) red[t] += red[t + s]; __syncthreads(); }
    float r = red[0]; __syncthreads(); return r;
}

__global__ void k_loss(const float* __restrict__ out, const int* __restrict__ tgt,
                       const float* __restrict__ ratio_p) {
    int n = blockIdx.x;
    int c = threadIdx.x;
    bool valid = (c < NC);
    int yn = tgt[n];
    float wy = g_w[yn];
    float ratio = ratio_p[0];
    __shared__ float red[256];
    float aug = -1e30f, augt = -1e30f;
    if (valid) {
        float yv = out[1 + n * NC + c];
        float q1 = (1.f - wy) * g_qcov[yn * NC + c] + g_qlow[yn * NC + c];
        float q2 = (1.f - wy) * g_qcov[NC * NC + yn * NC + c] + g_qlow[NC * NC + yn * NC + c];
        aug  = yv + 0.5f * ratio * q1;
        augt = yv + 0.5f * ratio * q2;
    }
    float mx  = blk_max(aug,  red);
    float mxt = blk_max(augt, red);
    float sa = blk_sum(valid ? expf(aug  - mx)  : 0.f, red);
    float sb = blk_sum(valid ? expf(augt - mxt) : 0.f, red);
    float lp  = aug  - mx  - logf(sa);
    float lpt = augt - mxt - logf(sb);
    float pt  = valid ? expf(lpt) : 0.f;
    float kln = blk_sum(valid ? pt * (lpt - lp) : 0.f, red);
    if (threadIdx.x == 0) g_kl[n] = kln;
    if (valid && c == yn) g_ce[n] = -lp;
}

__global__ void k_final(float* __restrict__ out) {
    __shared__ float red[256];
    int t = threadIdx.x;
    float v = g_ce[t] * (1.f / (float)NB) + g_kl[t] * (1.f / ((float)NB * (float)NC));
    red[t] = v; __syncthreads();
    for (int s = 128; s; s >>= 1) { if (t < s) red[t] += red[t + s]; __syncthreads(); }
    if (t == 0) out[0] = red[0];
}

extern "C" void kernel_launch(void* const* d_in, const int* in_sizes, int n_in,
                              void* d_out, int out_size) {
    const float* feat  = (const float*)d_in[0];
    const float* wfc   = (const float*)d_in[1];
    const float* bfc   = (const float*)d_in[2];
    const float* wfct  = (const float*)d_in[3];
    const float* cov   = (const float*)d_in[4];
    const float* Ave   = (const float*)d_in[5];
    const float* Amt   = (const float*)d_in[6];
    const int*   tgt   = (const int*)d_in[7];
    const float* ratio = (const float*)d_in[8];
    float* out = (float*)d_out;

    static bool init_done = false;
    static cudaStream_t sB;
    static cudaEvent_t evFork, evStats, evC;
    if (!init_done) {
        cudaFuncSetAttribute(k_gemm2, cudaFuncAttributeMaxDynamicSharedMemorySize, 3 * CBUF);
        cudaStreamCreateWithFlags(&sB, cudaStreamNonBlocking);
        cudaEventCreateWithFlags(&evFork, cudaEventDisableTiming);
        cudaEventCreateWithFlags(&evStats, cudaEventDisableTiming);
        cudaEventCreateWithFlags(&evC, cudaEventDisableTiming);
        init_done = true;
    }

    cudaEventRecord(evFork, 0);

    k_stats  <<<NC, 256>>>(feat, Ave, Amt, tgt);
    cudaEventRecord(evStats, 0);
    k_wconv  <<<MPAD, 256>>>(wfc, wfct);
    k_covcvt <<<dim3(NC, 36), 256>>>(cov);
    k_gemm2  <<<dim3(12, NC), 256, 3 * CBUF>>>();
    k_post   <<<dim3(NC, 4), 256>>>();

    cudaStreamWaitEvent(sB, evFork, 0);
    k_y      <<<32, 256, 0, sB>>>(feat, wfc, bfc, out);
    cudaStreamWaitEvent(sB, evStats, 0);
    k_lowrank<<<dim3(NC, 2), 256, 0, sB>>>(feat, wfc, wfct);
    cudaEventRecord(evC, sB);

    cudaStreamWaitEvent(0, evC, 0);
    k_loss   <<<NB, 256>>>(out, tgt, ratio);
    k_final  <<<1, 256>>>(out);
}